// round 15
// baseline (speedup 1.0000x reference)
#include <cuda_runtime.h>
#include <cuda_bf16.h>
#include <cuda_fp16.h>
#include <cstdint>
#include <cstddef>

#define BB 2
#define NN 2048
#define CC 768
#define HH 12
#define HD 64
#define BN (BB * NN)          // 4096
#define QKVC (3 * CC)         // 2304

// ---------------------------------------------------------------------------
// Scratch (device globals — no allocation allowed anywhere)
// ---------------------------------------------------------------------------
__device__ __align__(16) __half g_xh [(size_t)BN * CC];           // x fp16
__device__ __align__(16) __half g_wq [(size_t)QKVC * CC];         // Wqkv^T fp16
__device__ __align__(16) __half g_wp [(size_t)CC * CC];           // Wproj^T fp16
__device__ __align__(16) __half g_ah [(size_t)BN * CC];           // attn out fp16
// attention operands: [b][h][token][64] row-major, single fp16
__device__ __align__(16) __half g_qh[(size_t)BB * HH * NN * HD];
__device__ __align__(16) __half g_kh[(size_t)BB * HH * NN * HD];
__device__ __align__(16) __half g_vh[(size_t)BB * HH * NN * HD];
__device__ int g_kidx[BB * NN];
__device__ int g_kcnt[BB];

// ---------------------------------------------------------------------------
// PTX helpers (family-common; ptxas target is sm_103 w/o 'a')
// ---------------------------------------------------------------------------
__device__ __forceinline__ uint32_t smem_u32(const void* p) {
    uint32_t a;
    asm("{ .reg .u64 t; cvta.to.shared.u64 t, %1; cvt.u32.u64 %0, t; }"
        : "=r"(a) : "l"(p));
    return a;
}
#define CP_ASYNC16(dst, src) \
    asm volatile("cp.async.cg.shared.global [%0], [%1], 16;" :: "r"(dst), "l"(src))
#define CP_COMMIT() asm volatile("cp.async.commit_group;" ::: "memory")
#define CP_WAIT(n)  asm volatile("cp.async.wait_group %0;" :: "n"(n) : "memory")

#define LDSM_X4(r0, r1, r2, r3, addr)                                          \
    asm volatile("ldmatrix.sync.aligned.m8n8.x4.shared.b16 {%0,%1,%2,%3}, [%4];" \
                 : "=r"(r0), "=r"(r1), "=r"(r2), "=r"(r3) : "r"(addr))
#define LDSM_X4_T(r0, r1, r2, r3, addr)                                        \
    asm volatile("ldmatrix.sync.aligned.m8n8.x4.trans.shared.b16 {%0,%1,%2,%3}, [%4];" \
                 : "=r"(r0), "=r"(r1), "=r"(r2), "=r"(r3) : "r"(addr))

#define MMA16816H(d, a, b)                                                     \
    asm volatile("mma.sync.aligned.m16n8k16.row.col.f32.f16.f16.f32 "          \
                 "{%0,%1,%2,%3}, {%4,%5,%6,%7}, {%8,%9}, {%0,%1,%2,%3};"       \
                 : "+f"((d)[0]), "+f"((d)[1]), "+f"((d)[2]), "+f"((d)[3])      \
                 : "r"((a)[0]), "r"((a)[1]), "r"((a)[2]), "r"((a)[3]),         \
                   "r"((b)[0]), "r"((b)[1]))

__device__ __forceinline__ uint32_t pack_h2(float v0, float v1) {
    __half2 h = __floats2half2_rn(v0, v1);
    return *(uint32_t*)&h;
}

// ---------------------------------------------------------------------------
// MT2 fp16 GEMM pieces: 128x128 block tile, 8 warps as 2M x 4N (warp 64x32),
// K-chunk 32, 3-stage cp.async pipeline, paired-X4 B loads. Single fp16 A,B.
// ---------------------------------------------------------------------------
#define RS 40
#define MATB   (128 * RS * 2)           // 10240 (A and B each)
#define STAGE_P (2 * MATB)              // 20480
#define GEMM_SMEM (3 * STAGE_P)         // 61440

#define MT2_DECLS                                                              \
    extern __shared__ char smem[];                                             \
    const uint32_t sb = smem_u32(smem);                                        \
    const int tid = threadIdx.x, wid = tid >> 5, lane = tid & 31;              \
    const int wm = wid >> 2, wn = wid & 3;                                     \
    const int m_base = wm * 64, n_base = wn * 32;                              \
    const int a_r = (lane & 15);                                               \
    const int a_c = (lane >> 4) * 8;                                           \
    const int b4_r = ((lane >> 4) << 3) + (lane & 7);                          \
    const int b4_c = ((lane >> 3) & 1) * 8;

#define MT2_MAINLOOP(NCH)                                                      \
    prefetch(0, 0); CP_COMMIT();                                               \
    prefetch(1, 1); CP_COMMIT();                                               \
    for (int c = 0; c < (NCH); c++) {                                          \
        if (c + 1 < (NCH)) { CP_WAIT(1); } else { CP_WAIT(0); }                \
        __syncthreads();                                                       \
        if (c + 2 < (NCH)) { prefetch(c + 2, (c + 2) % 3); CP_COMMIT(); }      \
        const uint32_t As = sb + (c % 3) * STAGE_P;                            \
        const uint32_t Bs = As + MATB;                                         \
        _Pragma("unroll")                                                      \
        for (int kk = 0; kk < 2; kk++) {                                       \
            uint32_t ah[4][4];                                                 \
            _Pragma("unroll")                                                  \
            for (int mt = 0; mt < 4; mt++) {                                   \
                const uint32_t ao =                                            \
                    (uint32_t)((m_base + mt * 16 + a_r) * (RS * 2) +           \
                               (kk * 16 + a_c) * 2);                           \
                LDSM_X4(ah[mt][0], ah[mt][1], ah[mt][2], ah[mt][3], As + ao);  \
            }                                                                  \
            _Pragma("unroll")                                                  \
            for (int nt2 = 0; nt2 < 2; nt2++) {                                \
                const uint32_t bo =                                            \
                    (uint32_t)((n_base + nt2 * 16 + b4_r) * (RS * 2) +         \
                               (kk * 16 + b4_c) * 2);                          \
                uint32_t bv[4];                                                \
                LDSM_X4(bv[0], bv[1], bv[2], bv[3], Bs + bo);                  \
                _Pragma("unroll")                                              \
                for (int mt = 0; mt < 4; mt++) {                               \
                    MMA16816H(acc[mt][2 * nt2],     ah[mt], (bv));             \
                    MMA16816H(acc[mt][2 * nt2 + 1], ah[mt], (bv + 2));         \
                }                                                              \
            }                                                                  \
        }                                                                      \
    }

// A/B tile prefetch: 128 rows x 4 chunks each = 2 iters per matrix
#define MT2_PREFETCH_A(stage, Ap, m0, c)                                       \
    _Pragma("unroll")                                                          \
    for (int it = 0; it < 2; it++) {                                           \
        const int idx = it * 256 + tid;                                        \
        const int ra = idx >> 2, qa = idx & 3;                                 \
        CP_ASYNC16((stage) + (uint32_t)(ra * (RS * 2) + qa * 16),              \
                   (Ap) + (size_t)((m0) + ra) * 96 + (c) * 4 + qa);            \
    }
#define MT2_PREFETCH_B(stage, Bp, n0, c)                                       \
    _Pragma("unroll")                                                          \
    for (int it = 0; it < 2; it++) {                                           \
        const int idx = it * 256 + tid;                                        \
        const int rb = idx >> 2, qb = idx & 3;                                 \
        CP_ASYNC16((stage) + MATB + (uint32_t)(rb * (RS * 2) + qb * 16),       \
                   (Bp) + (size_t)((n0) + rb) * 96 + (c) * 4 + qb);            \
    }

// ---------------------------------------------------------------------------
// Proj GEMM: out[4096,768] = A(fp16)·Wp^T(fp16) + bias. Grid (6, 32).
// ---------------------------------------------------------------------------
__global__ __launch_bounds__(256) void gemm_proj(
    const uint4* __restrict__ Ah, const uint4* __restrict__ Bp,
    float* __restrict__ C, const float* __restrict__ bias)
{
    MT2_DECLS
    const int m0 = blockIdx.y * 128, n0 = blockIdx.x * 128;
    const int nch = CC >> 5;             // 24

    auto prefetch = [&](int c, int s) {
        const uint32_t stage = sb + s * STAGE_P;
        MT2_PREFETCH_A(stage, Ah, m0, c)
        MT2_PREFETCH_B(stage, Bp, n0, c)
    };

    float acc[4][4][4] = {};
    MT2_MAINLOOP(nch)

    #pragma unroll
    for (int mt = 0; mt < 4; mt++) {
        const int row0 = m0 + m_base + mt * 16 + (lane >> 2);
        #pragma unroll
        for (int nt = 0; nt < 4; nt++) {
            const int col = n0 + n_base + nt * 8 + (lane & 3) * 2;
            float b0 = bias[col], b1 = bias[col + 1];
            float2 v0 = { acc[mt][nt][0] + b0, acc[mt][nt][1] + b1 };
            float2 v1 = { acc[mt][nt][2] + b0, acc[mt][nt][3] + b1 };
            *(float2*)(C + (size_t)row0 * CC + col) = v0;
            *(float2*)(C + (size_t)(row0 + 8) * CC + col) = v1;
        }
    }
}

// ---------------------------------------------------------------------------
// Fused QKV GEMM (MT2): blocks [0,192) Q; [192,576) packed K/V.
// ---------------------------------------------------------------------------
__global__ __launch_bounds__(256) void qkv_fused(
    const uint4* __restrict__ Xh, const uint4* __restrict__ Wq,
    const int* __restrict__ kidx, const int* __restrict__ kcnt,
    __half* __restrict__ qh, __half* __restrict__ kh, __half* __restrict__ vh)
{
    MT2_DECLS
    const int bid = blockIdx.x;
    const int nch = CC >> 5;             // 24

    if (bid < 192) {
        // ------------------- Q role -------------------
        const int m0 = (bid / 6) * 128, n0 = (bid % 6) * 128;
        auto prefetch = [&](int c, int s) {
            const uint32_t stage = sb + s * STAGE_P;
            MT2_PREFETCH_A(stage, Xh, m0, c)
            MT2_PREFETCH_B(stage, Wq, n0, c)
        };
        float acc[4][4][4] = {};
        MT2_MAINLOOP(nch)

        #pragma unroll
        for (int mt = 0; mt < 4; mt++) {
            #pragma unroll
            for (int h2 = 0; h2 < 2; h2++) {
                const int r = m0 + m_base + mt * 16 + h2 * 8 + (lane >> 2);
                const int b = r >> 11, n = r & (NN - 1);
                #pragma unroll
                for (int nt = 0; nt < 4; nt++) {
                    const int c = n0 + n_base + nt * 8 + (lane & 3) * 2;
                    const int h = c >> 6, d = c & 63;
                    const size_t o = (((size_t)b * HH + h) * NN + n) * HD + d;
                    *(uint32_t*)((char*)qh + o * 2) =
                        pack_h2(acc[mt][nt][h2 * 2] * 0.125f,
                                acc[mt][nt][h2 * 2 + 1] * 0.125f);
                }
            }
        }
    } else {
        // ------------------- KV role (packed tokens) -------------------
        const int idx0 = bid - 192;
        const int bz = idx0 / 192;
        const int rr2 = idx0 % 192;
        const int m0 = (rr2 / 12) * 128;
        const int n0 = (rr2 % 12) * 128;
        const int cnt = kcnt[bz];
        const int pad = (cnt + 63) & ~63;
        if (m0 >= pad) return;

        const uint4* Bp = Wq + (size_t)CC * CC / 8;  // wq rows [768,2304)

        const int pr = tid >> 2, pq = tid & 3;
        const int j1 = m0 + pr, j2 = j1 + 64;
        const int s1 = (j1 < cnt) ? kidx[bz * NN + j1] : 0;
        const int s2 = (j2 < cnt) ? kidx[bz * NN + j2] : 0;

        auto prefetch = [&](int c, int s) {
            const uint32_t stage = sb + s * STAGE_P;
            #pragma unroll
            for (int it = 0; it < 2; it++) {
                const int ra = it * 64 + pr;
                const int srow = it ? s2 : s1;
                CP_ASYNC16(stage + (uint32_t)(ra * (RS * 2) + pq * 16),
                           Xh + (size_t)(bz * NN + srow) * 96 + c * 4 + pq);
            }
            MT2_PREFETCH_B(stage, Bp, n0, c)
        };
        float acc[4][4][4] = {};
        MT2_MAINLOOP(nch)

        #pragma unroll
        for (int mt = 0; mt < 4; mt++) {
            #pragma unroll
            for (int h2 = 0; h2 < 2; h2++) {
                const int j = m0 + m_base + mt * 16 + h2 * 8 + (lane >> 2);
                #pragma unroll
                for (int nt = 0; nt < 4; nt++) {
                    const int c = n0 + n_base + nt * 8 + (lane & 3) * 2;
                    const int isV = c >= CC;
                    const int cc = isV ? c - CC : c;
                    const int h = cc >> 6, d = cc & 63;
                    const size_t o = (((size_t)bz * HH + h) * NN + j) * HD + d;
                    __half* dst = isV ? vh : kh;
                    *(uint32_t*)((char*)dst + o * 2) =
                        pack_h2(acc[mt][nt][h2 * 2], acc[mt][nt][h2 * 2 + 1]);
                }
            }
        }
    }
}

// ---------------------------------------------------------------------------
// Fused pre-pass: [x->fp16 x8/thread][transpose wqkv][transpose wproj][scan]
// ---------------------------------------------------------------------------
#define PREP_SPLIT (BN * CC / 2048)         // 1536
#define PREP_TQ (72 * 24)                   // 1728
#define PREP_TP (24 * 24)                   // 576
#define PREP_TOTAL (PREP_SPLIT + PREP_TQ + PREP_TP + BB)

__global__ __launch_bounds__(256) void prep_all(
    const float* __restrict__ x, const int* __restrict__ mask,
    const float* __restrict__ w_qkv, const float* __restrict__ w_proj,
    __half* __restrict__ xh, __half* __restrict__ wq, __half* __restrict__ wp,
    int* __restrict__ kidx, int* __restrict__ kcnt)
{
    __shared__ float tbuf[32][33];
    __shared__ int part[256];
    const int bid = blockIdx.x, tid = threadIdx.x;

    if (bid < PREP_SPLIT) {
        const size_t i = ((size_t)bid * 256 + tid) * 8;
        float4 f0 = *(const float4*)(x + i);
        float4 f1 = *(const float4*)(x + i + 4);
        uint4 o;
        o.x = pack_h2(f0.x, f0.y);
        o.y = pack_h2(f0.z, f0.w);
        o.z = pack_h2(f1.x, f1.y);
        o.w = pack_h2(f1.z, f1.w);
        *(uint4*)(xh + i) = o;
    } else if (bid < PREP_SPLIT + PREP_TQ + PREP_TP) {
        const bool isQ = bid < PREP_SPLIT + PREP_TQ;
        const int t = isQ ? bid - PREP_SPLIT : bid - (PREP_SPLIT + PREP_TQ);
        const float* W = isQ ? w_qkv : w_proj;
        __half* dst = isQ ? wq : wp;
        const int N = isQ ? QKVC : CC;
        const int nblk = N / 32;
        const int n0 = (t % nblk) * 32, k0 = (t / nblk) * 32;
        const int tx = tid & 31, ty = tid >> 5;
        #pragma unroll
        for (int j = 0; j < 4; j++)
            tbuf[ty + 8 * j][tx] = W[(size_t)(k0 + ty + 8 * j) * N + n0 + tx];
        __syncthreads();
        #pragma unroll
        for (int j = 0; j < 4; j++) {
            const int nl = ty + 8 * j;
            dst[(size_t)(n0 + nl) * CC + k0 + tx] = __float2half_rn(tbuf[tx][nl]);
        }
    } else {
        const int b = bid - (PREP_SPLIT + PREP_TQ + PREP_TP);
        const int* m = mask + b * NN;
        int loc[8], c = 0;
        #pragma unroll
        for (int i = 0; i < 8; i++) { loc[i] = c; c += m[tid * 8 + i]; }
        part[tid] = c;
        __syncthreads();
        for (int off = 1; off < 256; off <<= 1) {
            int v = (tid >= off) ? part[tid - off] : 0;
            __syncthreads();
            part[tid] += v;
            __syncthreads();
        }
        int excl = part[tid] - c;
        #pragma unroll
        for (int i = 0; i < 8; i++)
            if (m[tid * 8 + i]) kidx[b * NN + excl + loc[i]] = tid * 8 + i;
        if (tid == 255) kcnt[b] = part[255];
    }
}

// ---------------------------------------------------------------------------
// Tensor-core attention: all-fp16, P-in-registers, paired X4 operand loads.
// (unchanged from R13/R14)
// ---------------------------------------------------------------------------
#define QT 128
#define KT 64
#define PADB 144                 // 72 x 16-bit per row
#define SM_STG  18432            // after Q resident
#define STG_SZ  18432            // K 9216 + V 9216
#define SM_RED  18432            // overlaid on stage area (post-loop only)
#define SM_DEN  55296
#define ATTN_SMEM (55296 + 512)

__global__ __launch_bounds__(256) void attn_mma(
    const uint4* __restrict__ Qh, const uint4* __restrict__ Kh,
    const uint4* __restrict__ Vh, const int* __restrict__ kcnt,
    __half* __restrict__ aout)
{
    extern __shared__ char sm[];
    const uint32_t sb = smem_u32(sm);
    const int b = blockIdx.z, h = blockIdx.y, q0 = blockIdx.x * QT;
    const int tid = threadIdx.x, wid = tid >> 5, lane = tid & 31;
    const int wm = wid >> 1, wn = wid & 1;
    const int mb = wm * 32, nb = wn * 32;
    const int cnt = kcnt[b];
    const int ntiles = (cnt + KT - 1) / KT;
    const size_t bh = (size_t)b * HH + h;

    float* denom_s = (float*)(sm + SM_DEN);
    if (tid < 128) denom_s[tid] = 0.0f;

    // resident Q tile (single fp16)
    #pragma unroll
    for (int it = 0; it < 4; it++) {
        int idx = it * 256 + tid;
        int r = idx >> 3, c = idx & 7;
        *(uint4*)(sm + r * PADB + c * 16) = Qh[(bh * NN + q0 + r) * 8 + c];
    }

    auto prefetch = [&](int t, int s) {
        const uint32_t stg = sb + SM_STG + s * STG_SZ;
        const int k0 = t * KT;
        #pragma unroll
        for (int it = 0; it < 4; it++) {
            int idx = it * 256 + tid;
            int mat = idx >> 9;                // 0 K, 1 V
            int r = (idx >> 3) & 63, c = idx & 7;
            uint32_t dst = stg + mat * 9216 + (uint32_t)(r * PADB + c * 16);
            const uint4* g = (mat == 0) ? Kh : Vh;
            CP_ASYNC16(dst, g + (bh * NN + k0 + r) * 8 + c);
        }
    };

    float accO[2][8][4] = {};
    float denA[2][2] = {};

    const int a_r = lane & 15, a_c = (lane >> 4) * 8;
    const int b4_r = ((lane >> 4) << 3) + (lane & 7);   // paired-K X4
    const int b4_c = ((lane >> 3) & 1) * 8;
    const int t_r = lane & 15;                          // V trans rows
    const int t_cext = (lane >> 4) * 16;                // V trans dt-pair col ext

    prefetch(0, 0);
    CP_COMMIT();

    for (int t = 0; t < ntiles; t++) {
        const int s = t & 1;
        const int k0 = t * KT;
        CP_WAIT(0);
        __syncthreads();
        if (t + 1 < ntiles) { prefetch(t + 1, 1 - s); CP_COMMIT(); }

        const uint32_t Ks = sb + SM_STG + s * STG_SZ;
        const uint32_t Vs = Ks + 9216;

        // S = Q K^T over this warp's 32q x 32k (fp16), K via paired X4
        float accS[2][4][4] = {};
        #pragma unroll
        for (int ks = 0; ks < 4; ks++) {
            uint32_t ah[2][4];
            #pragma unroll
            for (int mt = 0; mt < 2; mt++) {
                uint32_t ao = sb + (uint32_t)((mb + mt * 16 + a_r) * PADB +
                                              (ks * 16 + a_c) * 2);
                LDSM_X4(ah[mt][0], ah[mt][1], ah[mt][2], ah[mt][3], ao);
            }
            #pragma unroll
            for (int nt2 = 0; nt2 < 2; nt2++) {
                uint32_t bo = (uint32_t)((nb + nt2 * 16 + b4_r) * PADB +
                                         (ks * 16 + b4_c) * 2);
                uint32_t bv[4];
                LDSM_X4(bv[0], bv[1], bv[2], bv[3], Ks + bo);
                #pragma unroll
                for (int mt = 0; mt < 2; mt++) {
                    MMA16816H(accS[mt][2 * nt2],     ah[mt], (bv));
                    MMA16816H(accS[mt][2 * nt2 + 1], ah[mt], (bv + 2));
                }
            }
        }

        // exp + mask; P packed to fp16 A fragments
        uint32_t aP[2][2][4];
        #pragma unroll
        for (int mt = 0; mt < 2; mt++) {
            #pragma unroll
            for (int nt = 0; nt < 4; nt++) {
                int c0i = nb + nt * 8 + (lane & 3) * 2;
                float m0v = (k0 + c0i     < cnt) ? 1.f : 0.f;
                float m1v = (k0 + c0i + 1 < cnt) ? 1.f : 0.f;
                #pragma unroll
                for (int h2 = 0; h2 < 2; h2++) {
                    float p0 = __expf(accS[mt][nt][h2 * 2 + 0]) * m0v;
                    float p1 = __expf(accS[mt][nt][h2 * 2 + 1]) * m1v;
                    denA[mt][h2] += p0 + p1;
                    aP[mt][nt >> 1][(nt & 1) * 2 + h2] = pack_h2(p0, p1);
                }
            }
        }

        // O += P·V (fp16), V via paired X4 trans (two dt per load)
        #pragma unroll
        for (int kt = 0; kt < 2; kt++) {
            #pragma unroll
            for (int dt2 = 0; dt2 < 4; dt2++) {
                uint32_t bo = (uint32_t)((nb + kt * 16 + t_r) * PADB +
                                         dt2 * 32 + t_cext);
                uint32_t bv[4];
                LDSM_X4_T(bv[0], bv[1], bv[2], bv[3], Vs + bo);
                #pragma unroll
                for (int mt = 0; mt < 2; mt++) {
                    MMA16816H(accO[mt][2 * dt2],     aP[mt][kt], (bv));
                    MMA16816H(accO[mt][2 * dt2 + 1], aP[mt][kt], (bv + 2));
                }
            }
        }
    }

    // denom: quad-reduce then smem atomics
    #pragma unroll
    for (int mt = 0; mt < 2; mt++)
        #pragma unroll
        for (int h2 = 0; h2 < 2; h2++) {
            float v = denA[mt][h2];
            v += __shfl_xor_sync(0xffffffffu, v, 1);
            v += __shfl_xor_sync(0xffffffffu, v, 2);
            if ((lane & 3) == 0)
                atomicAdd(&denom_s[mb + mt * 16 + h2 * 8 + (lane >> 2)], v);
        }
    __syncthreads();

    // cross-pair O reduction: wn=1 stores to REDBUF (overlaid on stage area)
    float* red = (float*)(sm + SM_RED);
    if (wn == 1) {
        #pragma unroll
        for (int mt = 0; mt < 2; mt++) {
            const int r = mb + mt * 16 + (lane >> 2);
            #pragma unroll
            for (int dt = 0; dt < 8; dt++) {
                const int cc = dt * 8 + (lane & 3) * 2;
                *(float2*)&red[(size_t)r * 64 + cc] =
                    make_float2(accO[mt][dt][0], accO[mt][dt][1]);
                *(float2*)&red[(size_t)(r + 8) * 64 + cc] =
                    make_float2(accO[mt][dt][2], accO[mt][dt][3]);
            }
        }
    }
    __syncthreads();

    // wn=0 finalizes: add pair partial, divide, single-fp16 store
    if (wn == 0) {
        #pragma unroll
        for (int mt = 0; mt < 2; mt++) {
            const int r = mb + mt * 16 + (lane >> 2);
            const float inv0 = 1.0f / denom_s[r];
            const float inv1 = 1.0f / denom_s[r + 8];
            const size_t row0 = (size_t)(b * NN + q0 + r) * CC + h * HD;
            const size_t row1 = (size_t)(b * NN + q0 + r + 8) * CC + h * HD;
            #pragma unroll
            for (int dt = 0; dt < 8; dt++) {
                const int cc = dt * 8 + (lane & 3) * 2;
                float2 pr0 = *(float2*)&red[(size_t)r * 64 + cc];
                float2 pr1 = *(float2*)&red[(size_t)(r + 8) * 64 + cc];
                float v0 = (accO[mt][dt][0] + pr0.x) * inv0;
                float v1 = (accO[mt][dt][1] + pr0.y) * inv0;
                float v2 = (accO[mt][dt][2] + pr1.x) * inv1;
                float v3 = (accO[mt][dt][3] + pr1.y) * inv1;
                *(uint32_t*)((char*)aout + (row0 + cc) * 2) = pack_h2(v0, v1);
                *(uint32_t*)((char*)aout + (row1 + cc) * 2) = pack_h2(v2, v3);
            }
        }
    }
}

// ---------------------------------------------------------------------------
extern "C" void kernel_launch(void* const* d_in, const int* in_sizes, int n_in,
                              void* d_out, int out_size)
{
    const float* x      = (const float*)d_in[0];
    const int*   mask   = (const int*)  d_in[1];
    const float* w_qkv  = (const float*)d_in[2];
    const float* w_proj = (const float*)d_in[3];
    const float* b_proj = (const float*)d_in[4];
    float* out = (float*)d_out;

    __half *xh, *wq, *wp, *ah, *qh, *kh, *vh;
    int *kidx, *kcnt;
    cudaGetSymbolAddress((void**)&xh, g_xh);
    cudaGetSymbolAddress((void**)&wq, g_wq);
    cudaGetSymbolAddress((void**)&wp, g_wp);
    cudaGetSymbolAddress((void**)&ah, g_ah);
    cudaGetSymbolAddress((void**)&qh, g_qh);
    cudaGetSymbolAddress((void**)&kh, g_kh);
    cudaGetSymbolAddress((void**)&vh, g_vh);
    cudaGetSymbolAddress((void**)&kidx, g_kidx);
    cudaGetSymbolAddress((void**)&kcnt, g_kcnt);

    cudaFuncSetAttribute(gemm_proj, cudaFuncAttributeMaxDynamicSharedMemorySize, GEMM_SMEM);
    cudaFuncSetAttribute(qkv_fused, cudaFuncAttributeMaxDynamicSharedMemorySize, GEMM_SMEM);
    cudaFuncSetAttribute(attn_mma, cudaFuncAttributeMaxDynamicSharedMemorySize, ATTN_SMEM);

    // 0) fused pre-pass
    prep_all<<<PREP_TOTAL, 256>>>(x, mask, w_qkv, w_proj, xh, wq, wp, kidx, kcnt);

    // 1) fused Q + KV GEMM (MT2 128x128, 576 blocks)
    qkv_fused<<<576, 256, GEMM_SMEM>>>(
        (const uint4*)xh, (const uint4*)wq, kidx, kcnt, qh, kh, vh);

    // 2) tensor-core attention over packed keys (all-fp16)
    attn_mma<<<dim3(NN / QT, HH, BB), 256, ATTN_SMEM>>>(
        (const uint4*)qh, (const uint4*)kh, (const uint4*)vh, kcnt, ah);

    // 3) projection GEMM (MT2 128x128, 192 blocks) + bias
    gemm_proj<<<dim3(CC / 128, BN / 128), 256, GEMM_SMEM>>>(
        (const uint4*)ah, (const uint4*)wp, out, b_proj);
}

// round 16
// speedup vs baseline: 1.0745x; 1.0745x over previous
#include <cuda_runtime.h>
#include <cuda_bf16.h>
#include <cuda_fp16.h>
#include <cstdint>
#include <cstddef>

#define BB 2
#define NN 2048
#define CC 768
#define HH 12
#define HD 64
#define BN (BB * NN)          // 4096
#define QKVC (3 * CC)         // 2304

// ---------------------------------------------------------------------------
// Scratch (device globals — no allocation allowed anywhere)
// ---------------------------------------------------------------------------
__device__ __align__(16) __half g_xh [(size_t)BN * CC];           // x fp16
__device__ __align__(16) __half g_wq [(size_t)QKVC * CC];         // Wqkv^T fp16
__device__ __align__(16) __half g_wp [(size_t)CC * CC];           // Wproj^T fp16
__device__ __align__(16) __half g_ah [(size_t)BN * CC];           // attn out fp16
// attention operands: [b][h][token][64] row-major, single fp16
__device__ __align__(16) __half g_qh[(size_t)BB * HH * NN * HD];
__device__ __align__(16) __half g_kh[(size_t)BB * HH * NN * HD];
__device__ __align__(16) __half g_vh[(size_t)BB * HH * NN * HD];
__device__ int g_kidx[BB * NN];
__device__ int g_kcnt[BB];

// ---------------------------------------------------------------------------
// PTX helpers (family-common; ptxas target is sm_103 w/o 'a')
// ---------------------------------------------------------------------------
__device__ __forceinline__ uint32_t smem_u32(const void* p) {
    uint32_t a;
    asm("{ .reg .u64 t; cvta.to.shared.u64 t, %1; cvt.u32.u64 %0, t; }"
        : "=r"(a) : "l"(p));
    return a;
}
#define CP_ASYNC16(dst, src) \
    asm volatile("cp.async.cg.shared.global [%0], [%1], 16;" :: "r"(dst), "l"(src))
#define CP_COMMIT() asm volatile("cp.async.commit_group;" ::: "memory")
#define CP_WAIT(n)  asm volatile("cp.async.wait_group %0;" :: "n"(n) : "memory")

#define LDSM_X4(r0, r1, r2, r3, addr)                                          \
    asm volatile("ldmatrix.sync.aligned.m8n8.x4.shared.b16 {%0,%1,%2,%3}, [%4];" \
                 : "=r"(r0), "=r"(r1), "=r"(r2), "=r"(r3) : "r"(addr))
#define LDSM_X4_T(r0, r1, r2, r3, addr)                                        \
    asm volatile("ldmatrix.sync.aligned.m8n8.x4.trans.shared.b16 {%0,%1,%2,%3}, [%4];" \
                 : "=r"(r0), "=r"(r1), "=r"(r2), "=r"(r3) : "r"(addr))

#define MMA16816H(d, a, b)                                                     \
    asm volatile("mma.sync.aligned.m16n8k16.row.col.f32.f16.f16.f32 "          \
                 "{%0,%1,%2,%3}, {%4,%5,%6,%7}, {%8,%9}, {%0,%1,%2,%3};"       \
                 : "+f"((d)[0]), "+f"((d)[1]), "+f"((d)[2]), "+f"((d)[3])      \
                 : "r"((a)[0]), "r"((a)[1]), "r"((a)[2]), "r"((a)[3]),         \
                   "r"((b)[0]), "r"((b)[1]))

__device__ __forceinline__ uint32_t pack_h2(float v0, float v1) {
    __half2 h = __floats2half2_rn(v0, v1);
    return *(uint32_t*)&h;
}

// ---------------------------------------------------------------------------
// MT1 fp16 GEMM pieces (R14 config): 64x128 block tile, 8 warps 2M x 4N
// (warp 32x32), K-chunk 32, 3-stage cp.async pipeline, paired-X4 B loads.
// ---------------------------------------------------------------------------
#define RS 40
#define MAT_A  (64 * RS * 2)            // 5120
#define MAT_B  (128 * RS * 2)           // 10240
#define STAGE_P (MAT_A + MAT_B)         // 15360
#define GEMM_SMEM (3 * STAGE_P)         // 46080

#define MT1_DECLS                                                              \
    extern __shared__ char smem[];                                             \
    const uint32_t sb = smem_u32(smem);                                        \
    const int tid = threadIdx.x, wid = tid >> 5, lane = tid & 31;              \
    const int wm = wid >> 2, wn = wid & 3;                                     \
    const int m_base = wm * 32, n_base = wn * 32;                              \
    const int a_r = (lane & 15);                                               \
    const int a_c = (lane >> 4) * 8;                                           \
    const int b4_r = ((lane >> 4) << 3) + (lane & 7);                          \
    const int b4_c = ((lane >> 3) & 1) * 8;

#define MT1_MAINLOOP(NCH)                                                      \
    prefetch(0, 0); CP_COMMIT();                                               \
    prefetch(1, 1); CP_COMMIT();                                               \
    for (int c = 0; c < (NCH); c++) {                                          \
        if (c + 1 < (NCH)) { CP_WAIT(1); } else { CP_WAIT(0); }                \
        __syncthreads();                                                       \
        if (c + 2 < (NCH)) { prefetch(c + 2, (c + 2) % 3); CP_COMMIT(); }      \
        const uint32_t As = sb + (c % 3) * STAGE_P;                            \
        const uint32_t Bs = As + MAT_A;                                        \
        _Pragma("unroll")                                                      \
        for (int kk = 0; kk < 2; kk++) {                                       \
            uint32_t ah[2][4];                                                 \
            _Pragma("unroll")                                                  \
            for (int mt = 0; mt < 2; mt++) {                                   \
                const uint32_t ao =                                            \
                    (uint32_t)((m_base + mt * 16 + a_r) * (RS * 2) +           \
                               (kk * 16 + a_c) * 2);                           \
                LDSM_X4(ah[mt][0], ah[mt][1], ah[mt][2], ah[mt][3], As + ao);  \
            }                                                                  \
            _Pragma("unroll")                                                  \
            for (int nt2 = 0; nt2 < 2; nt2++) {                                \
                const uint32_t bo =                                            \
                    (uint32_t)((n_base + nt2 * 16 + b4_r) * (RS * 2) +         \
                               (kk * 16 + b4_c) * 2);                          \
                uint32_t bv[4];                                                \
                LDSM_X4(bv[0], bv[1], bv[2], bv[3], Bs + bo);                  \
                _Pragma("unroll")                                              \
                for (int mt = 0; mt < 2; mt++) {                               \
                    MMA16816H(acc[mt][2 * nt2],     ah[mt], (bv));             \
                    MMA16816H(acc[mt][2 * nt2 + 1], ah[mt], (bv + 2));         \
                }                                                              \
            }                                                                  \
        }                                                                      \
    }

// B prefetch: 128 rows x 4 chunks = 512 cp.async over 256 threads (2 iters)
#define MT1_PREFETCH_B(stage, Bp, n0, c)                                       \
    _Pragma("unroll")                                                          \
    for (int it = 0; it < 2; it++) {                                           \
        const int idx = it * 256 + tid;                                        \
        const int rb = idx >> 2, qb = idx & 3;                                 \
        CP_ASYNC16((stage) + MAT_A + (uint32_t)(rb * (RS * 2) + qb * 16),      \
                   (Bp) + (size_t)((n0) + rb) * 96 + (c) * 4 + qb);            \
    }

// ---------------------------------------------------------------------------
// Proj GEMM: out[4096,768] = A(fp16)·Wp^T(fp16) + bias. Grid (6, 64).
// ---------------------------------------------------------------------------
__global__ __launch_bounds__(256) void gemm_proj(
    const uint4* __restrict__ Ah, const uint4* __restrict__ Bp,
    float* __restrict__ C, const float* __restrict__ bias)
{
    MT1_DECLS
    const int m0 = blockIdx.y * 64, n0 = blockIdx.x * 128;
    const int nch = CC >> 5;             // 24

    auto prefetch = [&](int c, int s) {
        const uint32_t stage = sb + s * STAGE_P;
        const int r = tid >> 2, q = tid & 3;
        CP_ASYNC16(stage + (uint32_t)(r * (RS * 2) + q * 16),
                   Ah + (size_t)(m0 + r) * 96 + c * 4 + q);
        MT1_PREFETCH_B(stage, Bp, n0, c)
    };

    float acc[2][4][4] = {};
    MT1_MAINLOOP(nch)

    #pragma unroll
    for (int mt = 0; mt < 2; mt++) {
        const int row0 = m0 + m_base + mt * 16 + (lane >> 2);
        #pragma unroll
        for (int nt = 0; nt < 4; nt++) {
            const int col = n0 + n_base + nt * 8 + (lane & 3) * 2;
            float b0 = bias[col], b1 = bias[col + 1];
            float2 v0 = { acc[mt][nt][0] + b0, acc[mt][nt][1] + b1 };
            float2 v1 = { acc[mt][nt][2] + b0, acc[mt][nt][3] + b1 };
            *(float2*)(C + (size_t)row0 * CC + col) = v0;
            *(float2*)(C + (size_t)(row0 + 8) * CC + col) = v1;
        }
    }
}

// ---------------------------------------------------------------------------
// Fused QKV GEMM (MT1): blocks [0,384) Q; [384,1152) packed K/V.
// ---------------------------------------------------------------------------
__global__ __launch_bounds__(256) void qkv_fused(
    const uint4* __restrict__ Xh, const uint4* __restrict__ Wq,
    const int* __restrict__ kidx, const int* __restrict__ kcnt,
    __half* __restrict__ qh, __half* __restrict__ kh, __half* __restrict__ vh)
{
    MT1_DECLS
    const int bid = blockIdx.x;
    const int nch = CC >> 5;             // 24

    if (bid < 384) {
        // ------------------- Q role -------------------
        const int m0 = (bid / 6) * 64, n0 = (bid % 6) * 128;
        auto prefetch = [&](int c, int s) {
            const uint32_t stage = sb + s * STAGE_P;
            const int r = tid >> 2, q = tid & 3;
            CP_ASYNC16(stage + (uint32_t)(r * (RS * 2) + q * 16),
                       Xh + (size_t)(m0 + r) * 96 + c * 4 + q);
            MT1_PREFETCH_B(stage, Wq, n0, c)
        };
        float acc[2][4][4] = {};
        MT1_MAINLOOP(nch)

        #pragma unroll
        for (int mt = 0; mt < 2; mt++) {
            #pragma unroll
            for (int h2 = 0; h2 < 2; h2++) {
                const int r = m0 + m_base + mt * 16 + h2 * 8 + (lane >> 2);
                const int b = r >> 11, n = r & (NN - 1);
                #pragma unroll
                for (int nt = 0; nt < 4; nt++) {
                    const int c = n0 + n_base + nt * 8 + (lane & 3) * 2;
                    const int h = c >> 6, d = c & 63;
                    const size_t o = (((size_t)b * HH + h) * NN + n) * HD + d;
                    *(uint32_t*)((char*)qh + o * 2) =
                        pack_h2(acc[mt][nt][h2 * 2] * 0.125f,
                                acc[mt][nt][h2 * 2 + 1] * 0.125f);
                }
            }
        }
    } else {
        // ------------------- KV role (packed tokens) -------------------
        const int idx0 = bid - 384;
        const int bz = idx0 / 384;
        const int rr2 = idx0 % 384;
        const int m0 = (rr2 / 12) * 64;
        const int n0 = (rr2 % 12) * 128;
        const int cnt = kcnt[bz];
        const int pad = (cnt + 63) & ~63;
        if (m0 >= pad) return;

        const uint4* Bp = Wq + (size_t)CC * CC / 8;  // wq rows [768,2304)

        const int pr = tid >> 2, pq = tid & 3;
        const int j1 = m0 + pr;
        const int s1 = (j1 < cnt) ? kidx[bz * NN + j1] : 0;

        auto prefetch = [&](int c, int s) {
            const uint32_t stage = sb + s * STAGE_P;
            CP_ASYNC16(stage + (uint32_t)(pr * (RS * 2) + pq * 16),
                       Xh + (size_t)(bz * NN + s1) * 96 + c * 4 + pq);
            MT1_PREFETCH_B(stage, Bp, n0, c)
        };
        float acc[2][4][4] = {};
        MT1_MAINLOOP(nch)

        #pragma unroll
        for (int mt = 0; mt < 2; mt++) {
            #pragma unroll
            for (int h2 = 0; h2 < 2; h2++) {
                const int j = m0 + m_base + mt * 16 + h2 * 8 + (lane >> 2);
                #pragma unroll
                for (int nt = 0; nt < 4; nt++) {
                    const int c = n0 + n_base + nt * 8 + (lane & 3) * 2;
                    const int isV = c >= CC;
                    const int cc = isV ? c - CC : c;
                    const int h = cc >> 6, d = cc & 63;
                    const size_t o = (((size_t)bz * HH + h) * NN + j) * HD + d;
                    __half* dst = isV ? vh : kh;
                    *(uint32_t*)((char*)dst + o * 2) =
                        pack_h2(acc[mt][nt][h2 * 2], acc[mt][nt][h2 * 2 + 1]);
                }
            }
        }
    }
}

// ---------------------------------------------------------------------------
// Fused pre-pass: [x->fp16 x8/thread][transpose wqkv][transpose wproj][scan]
// ---------------------------------------------------------------------------
#define PREP_SPLIT (BN * CC / 2048)         // 1536
#define PREP_TQ (72 * 24)                   // 1728
#define PREP_TP (24 * 24)                   // 576
#define PREP_TOTAL (PREP_SPLIT + PREP_TQ + PREP_TP + BB)

__global__ __launch_bounds__(256) void prep_all(
    const float* __restrict__ x, const int* __restrict__ mask,
    const float* __restrict__ w_qkv, const float* __restrict__ w_proj,
    __half* __restrict__ xh, __half* __restrict__ wq, __half* __restrict__ wp,
    int* __restrict__ kidx, int* __restrict__ kcnt)
{
    __shared__ float tbuf[32][33];
    __shared__ int part[256];
    const int bid = blockIdx.x, tid = threadIdx.x;

    if (bid < PREP_SPLIT) {
        const size_t i = ((size_t)bid * 256 + tid) * 8;
        float4 f0 = *(const float4*)(x + i);
        float4 f1 = *(const float4*)(x + i + 4);
        uint4 o;
        o.x = pack_h2(f0.x, f0.y);
        o.y = pack_h2(f0.z, f0.w);
        o.z = pack_h2(f1.x, f1.y);
        o.w = pack_h2(f1.z, f1.w);
        *(uint4*)(xh + i) = o;
    } else if (bid < PREP_SPLIT + PREP_TQ + PREP_TP) {
        const bool isQ = bid < PREP_SPLIT + PREP_TQ;
        const int t = isQ ? bid - PREP_SPLIT : bid - (PREP_SPLIT + PREP_TQ);
        const float* W = isQ ? w_qkv : w_proj;
        __half* dst = isQ ? wq : wp;
        const int N = isQ ? QKVC : CC;
        const int nblk = N / 32;
        const int n0 = (t % nblk) * 32, k0 = (t / nblk) * 32;
        const int tx = tid & 31, ty = tid >> 5;
        #pragma unroll
        for (int j = 0; j < 4; j++)
            tbuf[ty + 8 * j][tx] = W[(size_t)(k0 + ty + 8 * j) * N + n0 + tx];
        __syncthreads();
        #pragma unroll
        for (int j = 0; j < 4; j++) {
            const int nl = ty + 8 * j;
            dst[(size_t)(n0 + nl) * CC + k0 + tx] = __float2half_rn(tbuf[tx][nl]);
        }
    } else {
        const int b = bid - (PREP_SPLIT + PREP_TQ + PREP_TP);
        const int* m = mask + b * NN;
        int loc[8], c = 0;
        #pragma unroll
        for (int i = 0; i < 8; i++) { loc[i] = c; c += m[tid * 8 + i]; }
        part[tid] = c;
        __syncthreads();
        for (int off = 1; off < 256; off <<= 1) {
            int v = (tid >= off) ? part[tid - off] : 0;
            __syncthreads();
            part[tid] += v;
            __syncthreads();
        }
        int excl = part[tid] - c;
        #pragma unroll
        for (int i = 0; i < 8; i++)
            if (m[tid * 8 + i]) kidx[b * NN + excl + loc[i]] = tid * 8 + i;
        if (tid == 255) kcnt[b] = part[255];
    }
}

// ---------------------------------------------------------------------------
// Tensor-core attention: all-fp16, P-in-registers, paired X4 operand loads,
// 3-stage K/V pipeline (CP_WAIT(1) — two tiles of load-ahead).
// ---------------------------------------------------------------------------
#define QT 128
#define KT 64
#define PADB 144                 // 72 x 16-bit per row
#define SM_STG  18432            // after Q resident
#define STG_SZ  18432            // K 9216 + V 9216
#define SM_RED  18432            // overlaid on stage area (post-loop only)
#define SM_DEN  (SM_STG + 3 * STG_SZ)       // 73728
#define ATTN_SMEM (SM_DEN + 512)            // 74240

__global__ __launch_bounds__(256) void attn_mma(
    const uint4* __restrict__ Qh, const uint4* __restrict__ Kh,
    const uint4* __restrict__ Vh, const int* __restrict__ kcnt,
    __half* __restrict__ aout)
{
    extern __shared__ char sm[];
    const uint32_t sb = smem_u32(sm);
    const int b = blockIdx.z, h = blockIdx.y, q0 = blockIdx.x * QT;
    const int tid = threadIdx.x, wid = tid >> 5, lane = tid & 31;
    const int wm = wid >> 1, wn = wid & 1;
    const int mb = wm * 32, nb = wn * 32;
    const int cnt = kcnt[b];
    const int ntiles = (cnt + KT - 1) / KT;
    const size_t bh = (size_t)b * HH + h;

    float* denom_s = (float*)(sm + SM_DEN);
    if (tid < 128) denom_s[tid] = 0.0f;

    // resident Q tile (single fp16)
    #pragma unroll
    for (int it = 0; it < 4; it++) {
        int idx = it * 256 + tid;
        int r = idx >> 3, c = idx & 7;
        *(uint4*)(sm + r * PADB + c * 16) = Qh[(bh * NN + q0 + r) * 8 + c];
    }

    auto prefetch = [&](int t, int s) {
        const uint32_t stg = sb + SM_STG + s * STG_SZ;
        const int k0 = t * KT;
        #pragma unroll
        for (int it = 0; it < 4; it++) {
            int idx = it * 256 + tid;
            int mat = idx >> 9;                // 0 K, 1 V
            int r = (idx >> 3) & 63, c = idx & 7;
            uint32_t dst = stg + mat * 9216 + (uint32_t)(r * PADB + c * 16);
            const uint4* g = (mat == 0) ? Kh : Vh;
            CP_ASYNC16(dst, g + (bh * NN + k0 + r) * 8 + c);
        }
    };

    float accO[2][8][4] = {};
    float denA[2][2] = {};

    const int a_r = lane & 15, a_c = (lane >> 4) * 8;
    const int b4_r = ((lane >> 4) << 3) + (lane & 7);   // paired-K X4
    const int b4_c = ((lane >> 3) & 1) * 8;
    const int t_r = lane & 15;                          // V trans rows
    const int t_cext = (lane >> 4) * 16;                // V trans dt-pair col ext

    prefetch(0, 0);
    CP_COMMIT();
    if (1 < ntiles) { prefetch(1, 1); CP_COMMIT(); }

    for (int t = 0; t < ntiles; t++) {
        const int k0 = t * KT;
        if (t + 1 < ntiles) { CP_WAIT(1); } else { CP_WAIT(0); }
        __syncthreads();
        if (t + 2 < ntiles) { prefetch(t + 2, (t + 2) % 3); CP_COMMIT(); }

        const uint32_t Ks = sb + SM_STG + (t % 3) * STG_SZ;
        const uint32_t Vs = Ks + 9216;

        // S = Q K^T over this warp's 32q x 32k (fp16), K via paired X4
        float accS[2][4][4] = {};
        #pragma unroll
        for (int ks = 0; ks < 4; ks++) {
            uint32_t ah[2][4];
            #pragma unroll
            for (int mt = 0; mt < 2; mt++) {
                uint32_t ao = sb + (uint32_t)((mb + mt * 16 + a_r) * PADB +
                                              (ks * 16 + a_c) * 2);
                LDSM_X4(ah[mt][0], ah[mt][1], ah[mt][2], ah[mt][3], ao);
            }
            #pragma unroll
            for (int nt2 = 0; nt2 < 2; nt2++) {
                uint32_t bo = (uint32_t)((nb + nt2 * 16 + b4_r) * PADB +
                                         (ks * 16 + b4_c) * 2);
                uint32_t bv[4];
                LDSM_X4(bv[0], bv[1], bv[2], bv[3], Ks + bo);
                #pragma unroll
                for (int mt = 0; mt < 2; mt++) {
                    MMA16816H(accS[mt][2 * nt2],     ah[mt], (bv));
                    MMA16816H(accS[mt][2 * nt2 + 1], ah[mt], (bv + 2));
                }
            }
        }

        // exp + mask; P packed to fp16 A fragments
        uint32_t aP[2][2][4];
        #pragma unroll
        for (int mt = 0; mt < 2; mt++) {
            #pragma unroll
            for (int nt = 0; nt < 4; nt++) {
                int c0i = nb + nt * 8 + (lane & 3) * 2;
                float m0v = (k0 + c0i     < cnt) ? 1.f : 0.f;
                float m1v = (k0 + c0i + 1 < cnt) ? 1.f : 0.f;
                #pragma unroll
                for (int h2 = 0; h2 < 2; h2++) {
                    float p0 = __expf(accS[mt][nt][h2 * 2 + 0]) * m0v;
                    float p1 = __expf(accS[mt][nt][h2 * 2 + 1]) * m1v;
                    denA[mt][h2] += p0 + p1;
                    aP[mt][nt >> 1][(nt & 1) * 2 + h2] = pack_h2(p0, p1);
                }
            }
        }

        // O += P·V (fp16), V via paired X4 trans (two dt per load)
        #pragma unroll
        for (int kt = 0; kt < 2; kt++) {
            #pragma unroll
            for (int dt2 = 0; dt2 < 4; dt2++) {
                uint32_t bo = (uint32_t)((nb + kt * 16 + t_r) * PADB +
                                         dt2 * 32 + t_cext);
                uint32_t bv[4];
                LDSM_X4_T(bv[0], bv[1], bv[2], bv[3], Vs + bo);
                #pragma unroll
                for (int mt = 0; mt < 2; mt++) {
                    MMA16816H(accO[mt][2 * dt2],     aP[mt][kt], (bv));
                    MMA16816H(accO[mt][2 * dt2 + 1], aP[mt][kt], (bv + 2));
                }
            }
        }
    }

    // denom: quad-reduce then smem atomics
    #pragma unroll
    for (int mt = 0; mt < 2; mt++)
        #pragma unroll
        for (int h2 = 0; h2 < 2; h2++) {
            float v = denA[mt][h2];
            v += __shfl_xor_sync(0xffffffffu, v, 1);
            v += __shfl_xor_sync(0xffffffffu, v, 2);
            if ((lane & 3) == 0)
                atomicAdd(&denom_s[mb + mt * 16 + h2 * 8 + (lane >> 2)], v);
        }
    __syncthreads();

    // cross-pair O reduction: wn=1 stores to REDBUF (overlaid on stage area)
    float* red = (float*)(sm + SM_RED);
    if (wn == 1) {
        #pragma unroll
        for (int mt = 0; mt < 2; mt++) {
            const int r = mb + mt * 16 + (lane >> 2);
            #pragma unroll
            for (int dt = 0; dt < 8; dt++) {
                const int cc = dt * 8 + (lane & 3) * 2;
                *(float2*)&red[(size_t)r * 64 + cc] =
                    make_float2(accO[mt][dt][0], accO[mt][dt][1]);
                *(float2*)&red[(size_t)(r + 8) * 64 + cc] =
                    make_float2(accO[mt][dt][2], accO[mt][dt][3]);
            }
        }
    }
    __syncthreads();

    // wn=0 finalizes: add pair partial, divide, single-fp16 store
    if (wn == 0) {
        #pragma unroll
        for (int mt = 0; mt < 2; mt++) {
            const int r = mb + mt * 16 + (lane >> 2);
            const float inv0 = 1.0f / denom_s[r];
            const float inv1 = 1.0f / denom_s[r + 8];
            const size_t row0 = (size_t)(b * NN + q0 + r) * CC + h * HD;
            const size_t row1 = (size_t)(b * NN + q0 + r + 8) * CC + h * HD;
            #pragma unroll
            for (int dt = 0; dt < 8; dt++) {
                const int cc = dt * 8 + (lane & 3) * 2;
                float2 pr0 = *(float2*)&red[(size_t)r * 64 + cc];
                float2 pr1 = *(float2*)&red[(size_t)(r + 8) * 64 + cc];
                float v0 = (accO[mt][dt][0] + pr0.x) * inv0;
                float v1 = (accO[mt][dt][1] + pr0.y) * inv0;
                float v2 = (accO[mt][dt][2] + pr1.x) * inv1;
                float v3 = (accO[mt][dt][3] + pr1.y) * inv1;
                *(uint32_t*)((char*)aout + (row0 + cc) * 2) = pack_h2(v0, v1);
                *(uint32_t*)((char*)aout + (row1 + cc) * 2) = pack_h2(v2, v3);
            }
        }
    }
}

// ---------------------------------------------------------------------------
extern "C" void kernel_launch(void* const* d_in, const int* in_sizes, int n_in,
                              void* d_out, int out_size)
{
    const float* x      = (const float*)d_in[0];
    const int*   mask   = (const int*)  d_in[1];
    const float* w_qkv  = (const float*)d_in[2];
    const float* w_proj = (const float*)d_in[3];
    const float* b_proj = (const float*)d_in[4];
    float* out = (float*)d_out;

    __half *xh, *wq, *wp, *ah, *qh, *kh, *vh;
    int *kidx, *kcnt;
    cudaGetSymbolAddress((void**)&xh, g_xh);
    cudaGetSymbolAddress((void**)&wq, g_wq);
    cudaGetSymbolAddress((void**)&wp, g_wp);
    cudaGetSymbolAddress((void**)&ah, g_ah);
    cudaGetSymbolAddress((void**)&qh, g_qh);
    cudaGetSymbolAddress((void**)&kh, g_kh);
    cudaGetSymbolAddress((void**)&vh, g_vh);
    cudaGetSymbolAddress((void**)&kidx, g_kidx);
    cudaGetSymbolAddress((void**)&kcnt, g_kcnt);

    cudaFuncSetAttribute(gemm_proj, cudaFuncAttributeMaxDynamicSharedMemorySize, GEMM_SMEM);
    cudaFuncSetAttribute(qkv_fused, cudaFuncAttributeMaxDynamicSharedMemorySize, GEMM_SMEM);
    cudaFuncSetAttribute(attn_mma, cudaFuncAttributeMaxDynamicSharedMemorySize, ATTN_SMEM);

    // 0) fused pre-pass
    prep_all<<<PREP_TOTAL, 256>>>(x, mask, w_qkv, w_proj, xh, wq, wp, kidx, kcnt);

    // 1) fused Q + KV GEMM (R14 config: MT1 64x128, 1152 blocks, 3-stage)
    qkv_fused<<<1152, 256, GEMM_SMEM>>>(
        (const uint4*)xh, (const uint4*)wq, kidx, kcnt, qh, kh, vh);

    // 2) tensor-core attention over packed keys (all-fp16, 3-stage pipeline)
    attn_mma<<<dim3(NN / QT, HH, BB), 256, ATTN_SMEM>>>(
        (const uint4*)qh, (const uint4*)kh, (const uint4*)vh, kcnt, ah);

    // 3) projection GEMM (R14 config: MT1 64x128, 384 blocks, 3-stage) + bias
    gemm_proj<<<dim3(CC / 128, BN / 64), 256, GEMM_SMEM>>>(
        (const uint4*)ah, (const uint4*)wp, out, b_proj);
}

// round 17
// speedup vs baseline: 1.0755x; 1.0009x over previous
#include <cuda_runtime.h>
#include <cuda_bf16.h>
#include <cuda_fp16.h>
#include <cstdint>
#include <cstddef>

#define BB 2
#define NN 2048
#define CC 768
#define HH 12
#define HD 64
#define BN (BB * NN)          // 4096
#define QKVC (3 * CC)         // 2304

// ---------------------------------------------------------------------------
// Scratch (device globals — no allocation allowed anywhere)
// ---------------------------------------------------------------------------
__device__ __align__(16) __half g_xh [(size_t)BN * CC];           // x fp16
__device__ __align__(16) __half g_wq [(size_t)QKVC * CC];         // Wqkv^T fp16
__device__ __align__(16) __half g_wp [(size_t)CC * CC];           // Wproj^T fp16
__device__ __align__(16) __half g_ah [(size_t)BN * CC];           // attn out fp16
// attention operands: [b][h][token][64] row-major, single fp16
__device__ __align__(16) __half g_qh[(size_t)BB * HH * NN * HD];
__device__ __align__(16) __half g_kh[(size_t)BB * HH * NN * HD];
__device__ __align__(16) __half g_vh[(size_t)BB * HH * NN * HD];
__device__ int g_kidx[BB * NN];
__device__ int g_kcnt[BB];

// ---------------------------------------------------------------------------
// PTX helpers (family-common; ptxas target is sm_103 w/o 'a')
// ---------------------------------------------------------------------------
__device__ __forceinline__ uint32_t smem_u32(const void* p) {
    uint32_t a;
    asm("{ .reg .u64 t; cvta.to.shared.u64 t, %1; cvt.u32.u64 %0, t; }"
        : "=r"(a) : "l"(p));
    return a;
}
#define CP_ASYNC16(dst, src) \
    asm volatile("cp.async.cg.shared.global [%0], [%1], 16;" :: "r"(dst), "l"(src))
#define CP_COMMIT() asm volatile("cp.async.commit_group;" ::: "memory")
#define CP_WAIT(n)  asm volatile("cp.async.wait_group %0;" :: "n"(n) : "memory")

#define LDSM_X4(r0, r1, r2, r3, addr)                                          \
    asm volatile("ldmatrix.sync.aligned.m8n8.x4.shared.b16 {%0,%1,%2,%3}, [%4];" \
                 : "=r"(r0), "=r"(r1), "=r"(r2), "=r"(r3) : "r"(addr))
#define LDSM_X4_T(r0, r1, r2, r3, addr)                                        \
    asm volatile("ldmatrix.sync.aligned.m8n8.x4.trans.shared.b16 {%0,%1,%2,%3}, [%4];" \
                 : "=r"(r0), "=r"(r1), "=r"(r2), "=r"(r3) : "r"(addr))

#define MMA16816H(d, a, b)                                                     \
    asm volatile("mma.sync.aligned.m16n8k16.row.col.f32.f16.f16.f32 "          \
                 "{%0,%1,%2,%3}, {%4,%5,%6,%7}, {%8,%9}, {%0,%1,%2,%3};"       \
                 : "+f"((d)[0]), "+f"((d)[1]), "+f"((d)[2]), "+f"((d)[3])      \
                 : "r"((a)[0]), "r"((a)[1]), "r"((a)[2]), "r"((a)[3]),         \
                   "r"((b)[0]), "r"((b)[1]))

__device__ __forceinline__ uint32_t pack_h2(float v0, float v1) {
    __half2 h = __floats2half2_rn(v0, v1);
    return *(uint32_t*)&h;
}

// ---------------------------------------------------------------------------
// MT1 fp16 GEMM pieces: 64x128 block tile, 8 warps 2M x 4N (warp 32x32),
// K-chunk 64 (12 iterations), 2-stage safe pipeline, paired-X4 B loads.
// Row stride 144B (conflict-free: r*144 mod 128 distinct over 8 rows).
// ---------------------------------------------------------------------------
#define RSB 144                          // bytes per smem row (64 fp16 + pad)
#define MAT_A  (64 * RSB)                // 9216
#define MAT_B  (128 * RSB)               // 18432
#define STAGE_P (MAT_A + MAT_B)          // 27648
#define GEMM_SMEM (2 * STAGE_P)          // 55296

#define MT1_DECLS                                                              \
    extern __shared__ char smem[];                                             \
    const uint32_t sb = smem_u32(smem);                                        \
    const int tid = threadIdx.x, wid = tid >> 5, lane = tid & 31;              \
    const int wm = wid >> 2, wn = wid & 3;                                     \
    const int m_base = wm * 32, n_base = wn * 32;                              \
    const int a_r = (lane & 15);                                               \
    const int a_c = (lane >> 4) * 8;                                           \
    const int b4_r = ((lane >> 4) << 3) + (lane & 7);                          \
    const int b4_c = ((lane >> 3) & 1) * 8;

// Safe 2-stage loop: WAIT(0) -> sync -> prefetch(c+1) -> compute(c).
#define MT1_MAINLOOP(NCH)                                                      \
    prefetch(0, 0); CP_COMMIT();                                               \
    for (int c = 0; c < (NCH); c++) {                                          \
        CP_WAIT(0);                                                            \
        __syncthreads();                                                       \
        if (c + 1 < (NCH)) { prefetch(c + 1, (c + 1) & 1); CP_COMMIT(); }      \
        const uint32_t As = sb + (c & 1) * STAGE_P;                            \
        const uint32_t Bs = As + MAT_A;                                        \
        _Pragma("unroll")                                                      \
        for (int kk = 0; kk < 4; kk++) {                                       \
            uint32_t ah[2][4];                                                 \
            _Pragma("unroll")                                                  \
            for (int mt = 0; mt < 2; mt++) {                                   \
                const uint32_t ao =                                            \
                    (uint32_t)((m_base + mt * 16 + a_r) * RSB +                \
                               (kk * 16 + a_c) * 2);                           \
                LDSM_X4(ah[mt][0], ah[mt][1], ah[mt][2], ah[mt][3], As + ao);  \
            }                                                                  \
            _Pragma("unroll")                                                  \
            for (int nt2 = 0; nt2 < 2; nt2++) {                                \
                const uint32_t bo =                                            \
                    (uint32_t)((n_base + nt2 * 16 + b4_r) * RSB +              \
                               (kk * 16 + b4_c) * 2);                          \
                uint32_t bv[4];                                                \
                LDSM_X4(bv[0], bv[1], bv[2], bv[3], Bs + bo);                  \
                _Pragma("unroll")                                              \
                for (int mt = 0; mt < 2; mt++) {                               \
                    MMA16816H(acc[mt][2 * nt2],     ah[mt], (bv));             \
                    MMA16816H(acc[mt][2 * nt2 + 1], ah[mt], (bv + 2));         \
                }                                                              \
            }                                                                  \
        }                                                                      \
    }

// A prefetch (dense rows): 64 rows x 8 chunks = 512 ops = 2 iters
#define MT1_PREFETCH_A(stage, Ap, m0, c)                                       \
    _Pragma("unroll")                                                          \
    for (int it = 0; it < 2; it++) {                                           \
        const int idx = it * 256 + tid;                                        \
        const int ra = idx >> 3, qa = idx & 7;                                 \
        CP_ASYNC16((stage) + (uint32_t)(ra * RSB + qa * 16),                   \
                   (Ap) + (size_t)((m0) + ra) * 96 + (c) * 8 + qa);            \
    }
// B prefetch: 128 rows x 8 chunks = 1024 ops = 4 iters
#define MT1_PREFETCH_B(stage, Bp, n0, c)                                       \
    _Pragma("unroll")                                                          \
    for (int it = 0; it < 4; it++) {                                           \
        const int idx = it * 256 + tid;                                        \
        const int rb = idx >> 3, qb = idx & 7;                                 \
        CP_ASYNC16((stage) + MAT_A + (uint32_t)(rb * RSB + qb * 16),           \
                   (Bp) + (size_t)((n0) + rb) * 96 + (c) * 8 + qb);            \
    }

// ---------------------------------------------------------------------------
// Proj GEMM: out[4096,768] = A(fp16)·Wp^T(fp16) + bias. Grid (6, 64).
// ---------------------------------------------------------------------------
__global__ __launch_bounds__(256) void gemm_proj(
    const uint4* __restrict__ Ah, const uint4* __restrict__ Bp,
    float* __restrict__ C, const float* __restrict__ bias)
{
    MT1_DECLS
    const int m0 = blockIdx.y * 64, n0 = blockIdx.x * 128;
    const int nch = CC >> 6;             // 12

    auto prefetch = [&](int c, int s) {
        const uint32_t stage = sb + s * STAGE_P;
        MT1_PREFETCH_A(stage, Ah, m0, c)
        MT1_PREFETCH_B(stage, Bp, n0, c)
    };

    float acc[2][4][4] = {};
    MT1_MAINLOOP(nch)

    #pragma unroll
    for (int mt = 0; mt < 2; mt++) {
        const int row0 = m0 + m_base + mt * 16 + (lane >> 2);
        #pragma unroll
        for (int nt = 0; nt < 4; nt++) {
            const int col = n0 + n_base + nt * 8 + (lane & 3) * 2;
            float b0 = bias[col], b1 = bias[col + 1];
            float2 v0 = { acc[mt][nt][0] + b0, acc[mt][nt][1] + b1 };
            float2 v1 = { acc[mt][nt][2] + b0, acc[mt][nt][3] + b1 };
            *(float2*)(C + (size_t)row0 * CC + col) = v0;
            *(float2*)(C + (size_t)(row0 + 8) * CC + col) = v1;
        }
    }
}

// ---------------------------------------------------------------------------
// Fused QKV GEMM (MT1): blocks [0,384) Q; [384,1152) packed K/V.
// ---------------------------------------------------------------------------
__global__ __launch_bounds__(256) void qkv_fused(
    const uint4* __restrict__ Xh, const uint4* __restrict__ Wq,
    const int* __restrict__ kidx, const int* __restrict__ kcnt,
    __half* __restrict__ qh, __half* __restrict__ kh, __half* __restrict__ vh)
{
    MT1_DECLS
    const int bid = blockIdx.x;
    const int nch = CC >> 6;             // 12

    if (bid < 384) {
        // ------------------- Q role -------------------
        const int m0 = (bid / 6) * 64, n0 = (bid % 6) * 128;
        auto prefetch = [&](int c, int s) {
            const uint32_t stage = sb + s * STAGE_P;
            MT1_PREFETCH_A(stage, Xh, m0, c)
            MT1_PREFETCH_B(stage, Wq, n0, c)
        };
        float acc[2][4][4] = {};
        MT1_MAINLOOP(nch)

        #pragma unroll
        for (int mt = 0; mt < 2; mt++) {
            #pragma unroll
            for (int h2 = 0; h2 < 2; h2++) {
                const int r = m0 + m_base + mt * 16 + h2 * 8 + (lane >> 2);
                const int b = r >> 11, n = r & (NN - 1);
                #pragma unroll
                for (int nt = 0; nt < 4; nt++) {
                    const int c = n0 + n_base + nt * 8 + (lane & 3) * 2;
                    const int h = c >> 6, d = c & 63;
                    const size_t o = (((size_t)b * HH + h) * NN + n) * HD + d;
                    *(uint32_t*)((char*)qh + o * 2) =
                        pack_h2(acc[mt][nt][h2 * 2] * 0.125f,
                                acc[mt][nt][h2 * 2 + 1] * 0.125f);
                }
            }
        }
    } else {
        // ------------------- KV role (packed tokens) -------------------
        const int idx0 = bid - 384;
        const int bz = idx0 / 384;
        const int rr2 = idx0 % 384;
        const int m0 = (rr2 / 12) * 64;
        const int n0 = (rr2 % 12) * 128;
        const int cnt = kcnt[bz];
        const int pad = (cnt + 63) & ~63;
        if (m0 >= pad) return;

        const uint4* Bp = Wq + (size_t)CC * CC / 8;  // wq rows [768,2304)

        // gathered source rows: each thread serves rows (tid>>3) and 32+(tid>>3)
        const int r0 = tid >> 3, pq = tid & 7;
        const int j0i = m0 + r0, j1i = m0 + 32 + r0;
        const int sA = (j0i < cnt) ? kidx[bz * NN + j0i] : 0;
        const int sB = (j1i < cnt) ? kidx[bz * NN + j1i] : 0;

        auto prefetch = [&](int c, int s) {
            const uint32_t stage = sb + s * STAGE_P;
            #pragma unroll
            for (int it = 0; it < 2; it++) {
                const int ra = it * 32 + r0;
                const int srow = it ? sB : sA;
                CP_ASYNC16(stage + (uint32_t)(ra * RSB + pq * 16),
                           Xh + (size_t)(bz * NN + srow) * 96 + c * 8 + pq);
            }
            MT1_PREFETCH_B(stage, Bp, n0, c)
        };
        float acc[2][4][4] = {};
        MT1_MAINLOOP(nch)

        #pragma unroll
        for (int mt = 0; mt < 2; mt++) {
            #pragma unroll
            for (int h2 = 0; h2 < 2; h2++) {
                const int j = m0 + m_base + mt * 16 + h2 * 8 + (lane >> 2);
                #pragma unroll
                for (int nt = 0; nt < 4; nt++) {
                    const int c = n0 + n_base + nt * 8 + (lane & 3) * 2;
                    const int isV = c >= CC;
                    const int cc = isV ? c - CC : c;
                    const int h = cc >> 6, d = cc & 63;
                    const size_t o = (((size_t)bz * HH + h) * NN + j) * HD + d;
                    __half* dst = isV ? vh : kh;
                    *(uint32_t*)((char*)dst + o * 2) =
                        pack_h2(acc[mt][nt][h2 * 2], acc[mt][nt][h2 * 2 + 1]);
                }
            }
        }
    }
}

// ---------------------------------------------------------------------------
// Fused pre-pass: [x->fp16 x8/thread][transpose wqkv][transpose wproj][scan]
// ---------------------------------------------------------------------------
#define PREP_SPLIT (BN * CC / 2048)         // 1536
#define PREP_TQ (72 * 24)                   // 1728
#define PREP_TP (24 * 24)                   // 576
#define PREP_TOTAL (PREP_SPLIT + PREP_TQ + PREP_TP + BB)

__global__ __launch_bounds__(256) void prep_all(
    const float* __restrict__ x, const int* __restrict__ mask,
    const float* __restrict__ w_qkv, const float* __restrict__ w_proj,
    __half* __restrict__ xh, __half* __restrict__ wq, __half* __restrict__ wp,
    int* __restrict__ kidx, int* __restrict__ kcnt)
{
    __shared__ float tbuf[32][33];
    __shared__ int part[256];
    const int bid = blockIdx.x, tid = threadIdx.x;

    if (bid < PREP_SPLIT) {
        const size_t i = ((size_t)bid * 256 + tid) * 8;
        float4 f0 = *(const float4*)(x + i);
        float4 f1 = *(const float4*)(x + i + 4);
        uint4 o;
        o.x = pack_h2(f0.x, f0.y);
        o.y = pack_h2(f0.z, f0.w);
        o.z = pack_h2(f1.x, f1.y);
        o.w = pack_h2(f1.z, f1.w);
        *(uint4*)(xh + i) = o;
    } else if (bid < PREP_SPLIT + PREP_TQ + PREP_TP) {
        const bool isQ = bid < PREP_SPLIT + PREP_TQ;
        const int t = isQ ? bid - PREP_SPLIT : bid - (PREP_SPLIT + PREP_TQ);
        const float* W = isQ ? w_qkv : w_proj;
        __half* dst = isQ ? wq : wp;
        const int N = isQ ? QKVC : CC;
        const int nblk = N / 32;
        const int n0 = (t % nblk) * 32, k0 = (t / nblk) * 32;
        const int tx = tid & 31, ty = tid >> 5;
        #pragma unroll
        for (int j = 0; j < 4; j++)
            tbuf[ty + 8 * j][tx] = W[(size_t)(k0 + ty + 8 * j) * N + n0 + tx];
        __syncthreads();
        #pragma unroll
        for (int j = 0; j < 4; j++) {
            const int nl = ty + 8 * j;
            dst[(size_t)(n0 + nl) * CC + k0 + tx] = __float2half_rn(tbuf[tx][nl]);
        }
    } else {
        const int b = bid - (PREP_SPLIT + PREP_TQ + PREP_TP);
        const int* m = mask + b * NN;
        int loc[8], c = 0;
        #pragma unroll
        for (int i = 0; i < 8; i++) { loc[i] = c; c += m[tid * 8 + i]; }
        part[tid] = c;
        __syncthreads();
        for (int off = 1; off < 256; off <<= 1) {
            int v = (tid >= off) ? part[tid - off] : 0;
            __syncthreads();
            part[tid] += v;
            __syncthreads();
        }
        int excl = part[tid] - c;
        #pragma unroll
        for (int i = 0; i < 8; i++)
            if (m[tid * 8 + i]) kidx[b * NN + excl + loc[i]] = tid * 8 + i;
        if (tid == 255) kcnt[b] = part[255];
    }
}

// ---------------------------------------------------------------------------
// Tensor-core attention (R14 config): all-fp16, P-in-registers, paired X4,
// 2-stage safe pipeline.
// ---------------------------------------------------------------------------
#define QT 128
#define KT 64
#define PADB 144                 // 72 x 16-bit per row
#define SM_STG  18432            // after Q resident
#define STG_SZ  18432            // K 9216 + V 9216
#define SM_RED  18432            // overlaid on stage area (post-loop only)
#define SM_DEN  55296
#define ATTN_SMEM (55296 + 512)

__global__ __launch_bounds__(256) void attn_mma(
    const uint4* __restrict__ Qh, const uint4* __restrict__ Kh,
    const uint4* __restrict__ Vh, const int* __restrict__ kcnt,
    __half* __restrict__ aout)
{
    extern __shared__ char sm[];
    const uint32_t sb = smem_u32(sm);
    const int b = blockIdx.z, h = blockIdx.y, q0 = blockIdx.x * QT;
    const int tid = threadIdx.x, wid = tid >> 5, lane = tid & 31;
    const int wm = wid >> 1, wn = wid & 1;
    const int mb = wm * 32, nb = wn * 32;
    const int cnt = kcnt[b];
    const int ntiles = (cnt + KT - 1) / KT;
    const size_t bh = (size_t)b * HH + h;

    float* denom_s = (float*)(sm + SM_DEN);
    if (tid < 128) denom_s[tid] = 0.0f;

    // resident Q tile (single fp16)
    #pragma unroll
    for (int it = 0; it < 4; it++) {
        int idx = it * 256 + tid;
        int r = idx >> 3, c = idx & 7;
        *(uint4*)(sm + r * PADB + c * 16) = Qh[(bh * NN + q0 + r) * 8 + c];
    }

    auto prefetch = [&](int t, int s) {
        const uint32_t stg = sb + SM_STG + s * STG_SZ;
        const int k0 = t * KT;
        #pragma unroll
        for (int it = 0; it < 4; it++) {
            int idx = it * 256 + tid;
            int mat = idx >> 9;                // 0 K, 1 V
            int r = (idx >> 3) & 63, c = idx & 7;
            uint32_t dst = stg + mat * 9216 + (uint32_t)(r * PADB + c * 16);
            const uint4* g = (mat == 0) ? Kh : Vh;
            CP_ASYNC16(dst, g + (bh * NN + k0 + r) * 8 + c);
        }
    };

    float accO[2][8][4] = {};
    float denA[2][2] = {};

    const int a_r = lane & 15, a_c = (lane >> 4) * 8;
    const int b4_r = ((lane >> 4) << 3) + (lane & 7);   // paired-K X4
    const int b4_c = ((lane >> 3) & 1) * 8;
    const int t_r = lane & 15;                          // V trans rows
    const int t_cext = (lane >> 4) * 16;                // V trans dt-pair col ext

    prefetch(0, 0);
    CP_COMMIT();

    for (int t = 0; t < ntiles; t++) {
        const int s = t & 1;
        const int k0 = t * KT;
        CP_WAIT(0);
        __syncthreads();
        if (t + 1 < ntiles) { prefetch(t + 1, 1 - s); CP_COMMIT(); }

        const uint32_t Ks = sb + SM_STG + s * STG_SZ;
        const uint32_t Vs = Ks + 9216;

        // S = Q K^T over this warp's 32q x 32k (fp16), K via paired X4
        float accS[2][4][4] = {};
        #pragma unroll
        for (int ks = 0; ks < 4; ks++) {
            uint32_t ah[2][4];
            #pragma unroll
            for (int mt = 0; mt < 2; mt++) {
                uint32_t ao = sb + (uint32_t)((mb + mt * 16 + a_r) * PADB +
                                              (ks * 16 + a_c) * 2);
                LDSM_X4(ah[mt][0], ah[mt][1], ah[mt][2], ah[mt][3], ao);
            }
            #pragma unroll
            for (int nt2 = 0; nt2 < 2; nt2++) {
                uint32_t bo = (uint32_t)((nb + nt2 * 16 + b4_r) * PADB +
                                         (ks * 16 + b4_c) * 2);
                uint32_t bv[4];
                LDSM_X4(bv[0], bv[1], bv[2], bv[3], Ks + bo);
                #pragma unroll
                for (int mt = 0; mt < 2; mt++) {
                    MMA16816H(accS[mt][2 * nt2],     ah[mt], (bv));
                    MMA16816H(accS[mt][2 * nt2 + 1], ah[mt], (bv + 2));
                }
            }
        }

        // exp + mask; P packed to fp16 A fragments
        uint32_t aP[2][2][4];
        #pragma unroll
        for (int mt = 0; mt < 2; mt++) {
            #pragma unroll
            for (int nt = 0; nt < 4; nt++) {
                int c0i = nb + nt * 8 + (lane & 3) * 2;
                float m0v = (k0 + c0i     < cnt) ? 1.f : 0.f;
                float m1v = (k0 + c0i + 1 < cnt) ? 1.f : 0.f;
                #pragma unroll
                for (int h2 = 0; h2 < 2; h2++) {
                    float p0 = __expf(accS[mt][nt][h2 * 2 + 0]) * m0v;
                    float p1 = __expf(accS[mt][nt][h2 * 2 + 1]) * m1v;
                    denA[mt][h2] += p0 + p1;
                    aP[mt][nt >> 1][(nt & 1) * 2 + h2] = pack_h2(p0, p1);
                }
            }
        }

        // O += P·V (fp16), V via paired X4 trans (two dt per load)
        #pragma unroll
        for (int kt = 0; kt < 2; kt++) {
            #pragma unroll
            for (int dt2 = 0; dt2 < 4; dt2++) {
                uint32_t bo = (uint32_t)((nb + kt * 16 + t_r) * PADB +
                                         dt2 * 32 + t_cext);
                uint32_t bv[4];
                LDSM_X4_T(bv[0], bv[1], bv[2], bv[3], Vs + bo);
                #pragma unroll
                for (int mt = 0; mt < 2; mt++) {
                    MMA16816H(accO[mt][2 * dt2],     aP[mt][kt], (bv));
                    MMA16816H(accO[mt][2 * dt2 + 1], aP[mt][kt], (bv + 2));
                }
            }
        }
    }

    // denom: quad-reduce then smem atomics
    #pragma unroll
    for (int mt = 0; mt < 2; mt++)
        #pragma unroll
        for (int h2 = 0; h2 < 2; h2++) {
            float v = denA[mt][h2];
            v += __shfl_xor_sync(0xffffffffu, v, 1);
            v += __shfl_xor_sync(0xffffffffu, v, 2);
            if ((lane & 3) == 0)
                atomicAdd(&denom_s[mb + mt * 16 + h2 * 8 + (lane >> 2)], v);
        }
    __syncthreads();

    // cross-pair O reduction: wn=1 stores to REDBUF (overlaid on stage area)
    float* red = (float*)(sm + SM_RED);
    if (wn == 1) {
        #pragma unroll
        for (int mt = 0; mt < 2; mt++) {
            const int r = mb + mt * 16 + (lane >> 2);
            #pragma unroll
            for (int dt = 0; dt < 8; dt++) {
                const int cc = dt * 8 + (lane & 3) * 2;
                *(float2*)&red[(size_t)r * 64 + cc] =
                    make_float2(accO[mt][dt][0], accO[mt][dt][1]);
                *(float2*)&red[(size_t)(r + 8) * 64 + cc] =
                    make_float2(accO[mt][dt][2], accO[mt][dt][3]);
            }
        }
    }
    __syncthreads();

    // wn=0 finalizes: add pair partial, divide, single-fp16 store
    if (wn == 0) {
        #pragma unroll
        for (int mt = 0; mt < 2; mt++) {
            const int r = mb + mt * 16 + (lane >> 2);
            const float inv0 = 1.0f / denom_s[r];
            const float inv1 = 1.0f / denom_s[r + 8];
            const size_t row0 = (size_t)(b * NN + q0 + r) * CC + h * HD;
            const size_t row1 = (size_t)(b * NN + q0 + r + 8) * CC + h * HD;
            #pragma unroll
            for (int dt = 0; dt < 8; dt++) {
                const int cc = dt * 8 + (lane & 3) * 2;
                float2 pr0 = *(float2*)&red[(size_t)r * 64 + cc];
                float2 pr1 = *(float2*)&red[(size_t)(r + 8) * 64 + cc];
                float v0 = (accO[mt][dt][0] + pr0.x) * inv0;
                float v1 = (accO[mt][dt][1] + pr0.y) * inv0;
                float v2 = (accO[mt][dt][2] + pr1.x) * inv1;
                float v3 = (accO[mt][dt][3] + pr1.y) * inv1;
                *(uint32_t*)((char*)aout + (row0 + cc) * 2) = pack_h2(v0, v1);
                *(uint32_t*)((char*)aout + (row1 + cc) * 2) = pack_h2(v2, v3);
            }
        }
    }
}

// ---------------------------------------------------------------------------
extern "C" void kernel_launch(void* const* d_in, const int* in_sizes, int n_in,
                              void* d_out, int out_size)
{
    const float* x      = (const float*)d_in[0];
    const int*   mask   = (const int*)  d_in[1];
    const float* w_qkv  = (const float*)d_in[2];
    const float* w_proj = (const float*)d_in[3];
    const float* b_proj = (const float*)d_in[4];
    float* out = (float*)d_out;

    __half *xh, *wq, *wp, *ah, *qh, *kh, *vh;
    int *kidx, *kcnt;
    cudaGetSymbolAddress((void**)&xh, g_xh);
    cudaGetSymbolAddress((void**)&wq, g_wq);
    cudaGetSymbolAddress((void**)&wp, g_wp);
    cudaGetSymbolAddress((void**)&ah, g_ah);
    cudaGetSymbolAddress((void**)&qh, g_qh);
    cudaGetSymbolAddress((void**)&kh, g_kh);
    cudaGetSymbolAddress((void**)&vh, g_vh);
    cudaGetSymbolAddress((void**)&kidx, g_kidx);
    cudaGetSymbolAddress((void**)&kcnt, g_kcnt);

    cudaFuncSetAttribute(gemm_proj, cudaFuncAttributeMaxDynamicSharedMemorySize, GEMM_SMEM);
    cudaFuncSetAttribute(qkv_fused, cudaFuncAttributeMaxDynamicSharedMemorySize, GEMM_SMEM);
    cudaFuncSetAttribute(attn_mma, cudaFuncAttributeMaxDynamicSharedMemorySize, ATTN_SMEM);

    // 0) fused pre-pass
    prep_all<<<PREP_TOTAL, 256>>>(x, mask, w_qkv, w_proj, xh, wq, wp, kidx, kcnt);

    // 1) fused Q + KV GEMM (K-chunk 64, 12 iterations)
    qkv_fused<<<1152, 256, GEMM_SMEM>>>(
        (const uint4*)xh, (const uint4*)wq, kidx, kcnt, qh, kh, vh);

    // 2) tensor-core attention over packed keys (R14 config)
    attn_mma<<<dim3(NN / QT, HH, BB), 256, ATTN_SMEM>>>(
        (const uint4*)qh, (const uint4*)kh, (const uint4*)vh, kcnt, ah);

    // 3) projection GEMM (K-chunk 64) + bias
    gemm_proj<<<dim3(CC / 128, BN / 64), 256, GEMM_SMEM>>>(
        (const uint4*)ah, (const uint4*)wp, out, b_proj);
}